// round 3
// baseline (speedup 1.0000x reference)
#include <cuda_runtime.h>
#include <cuda_bf16.h>

// ---------------------------------------------------------------------------
// AxialAttention (K=56, G=8, CIN=512, COUT=512) — fp32 SIMT baseline
//   k1: fused QKV GEMM [50176 x 512] x [512 x 1024] + BN fold, writes
//       Q/K/V transposed to [b][w][row][c] for downstream locality
//   k2: per-(b,w) logits  L[g][i][j] = s_qk*QK + s_qr*Qr + s_kr*Kr + t
//   k3: in-place softmax over w (the faithful axis=-2)
//   k4: per-(b,w) sv/sve GEMMs + final BN fold -> out [b][i][w][512]
// ---------------------------------------------------------------------------

#define EPS 1e-3f

// scratch (static device arrays: allocation-free rule)
__device__ float g_Q[12845056];   // [16][56 w][56 i][256]
__device__ float g_K[12845056];   // [16][56 w][56 j][256]
__device__ float g_V[25690112];   // [16][56 w][56 j][512]
__device__ float g_L[22478848];   // [16][56 w][8 g][3136 ij]  (logits -> sim in place)

__device__ __forceinline__ float dot4(float4 a, float4 b) {
    return a.x*b.x + a.y*b.y + a.z*b.z + a.w*b.w;
}

// ---------------------------------------------------------------------------
// k1: QKV GEMM, BM=128 BN=128 BK=16, 256 thr, 8x8 microtile, dbl-buffered
// ---------------------------------------------------------------------------
__global__ __launch_bounds__(256, 2) void qkv_gemm_kernel(
    const float* __restrict__ x,
    const float* __restrict__ Wq, const float* __restrict__ Wk, const float* __restrict__ Wv,
    const float* __restrict__ pq, const float* __restrict__ pk, const float* __restrict__ pv)
{
    __shared__ float As[2][16][132];
    __shared__ float Bs[2][16][132];

    const int tid = threadIdx.x;
    const int n0  = blockIdx.x * 128;   // 0..1023
    const int m0  = blockIdx.y * 128;   // 0..50048

    const float* W; const float* P; float* dst; int ncols, colbase;
    if (n0 < 256)      { W = Wq; P = pq; dst = g_Q; ncols = 256; colbase = n0;       }
    else if (n0 < 512) { W = Wk; P = pk; dst = g_K; ncols = 256; colbase = n0 - 256; }
    else               { W = Wv; P = pv; dst = g_V; ncols = 512; colbase = n0 - 512; }

    const int ra = tid >> 2;          // 0..63
    const int ca = (tid & 3) << 2;    // 0,4,8,12
    const int kb = tid >> 4;          // 0..15
    const int nb = (tid & 15) << 3;   // 0..120
    const int ty = tid >> 4;          // 0..15
    const int tx = tid & 15;          // 0..15

    float acc[8][8];
    #pragma unroll
    for (int a = 0; a < 8; a++)
        #pragma unroll
        for (int c = 0; c < 8; c++) acc[a][c] = 0.f;

    // prologue: tile 0
    {
        float4 a0 = *(const float4*)(x + (m0 + ra) * 512 + ca);
        float4 a1 = *(const float4*)(x + (m0 + 64 + ra) * 512 + ca);
        float4 b0 = *(const float4*)(W + kb * ncols + colbase + nb);
        float4 b1 = *(const float4*)(W + kb * ncols + colbase + nb + 4);
        As[0][ca+0][ra] = a0.x; As[0][ca+1][ra] = a0.y;
        As[0][ca+2][ra] = a0.z; As[0][ca+3][ra] = a0.w;
        As[0][ca+0][64+ra] = a1.x; As[0][ca+1][64+ra] = a1.y;
        As[0][ca+2][64+ra] = a1.z; As[0][ca+3][64+ra] = a1.w;
        *(float4*)(&Bs[0][kb][nb])   = b0;
        *(float4*)(&Bs[0][kb][nb+4]) = b1;
    }
    __syncthreads();

    for (int ks = 0; ks < 32; ks++) {
        const int cur = ks & 1;
        float4 a0, a1, b0, b1;
        if (ks < 31) {
            const int k0 = (ks + 1) * 16;
            a0 = *(const float4*)(x + (m0 + ra) * 512 + k0 + ca);
            a1 = *(const float4*)(x + (m0 + 64 + ra) * 512 + k0 + ca);
            b0 = *(const float4*)(W + (k0 + kb) * ncols + colbase + nb);
            b1 = *(const float4*)(W + (k0 + kb) * ncols + colbase + nb + 4);
        }
        #pragma unroll
        for (int kk = 0; kk < 16; kk++) {
            float a[8], b[8];
            *(float4*)&a[0] = *(const float4*)&As[cur][kk][ty*8];
            *(float4*)&a[4] = *(const float4*)&As[cur][kk][ty*8+4];
            *(float4*)&b[0] = *(const float4*)&Bs[cur][kk][tx*8];
            *(float4*)&b[4] = *(const float4*)&Bs[cur][kk][tx*8+4];
            #pragma unroll
            for (int i2 = 0; i2 < 8; i2++)
                #pragma unroll
                for (int j2 = 0; j2 < 8; j2++)
                    acc[i2][j2] = fmaf(a[i2], b[j2], acc[i2][j2]);
        }
        if (ks < 31) {
            const int nxt = cur ^ 1;
            As[nxt][ca+0][ra] = a0.x; As[nxt][ca+1][ra] = a0.y;
            As[nxt][ca+2][ra] = a0.z; As[nxt][ca+3][ra] = a0.w;
            As[nxt][ca+0][64+ra] = a1.x; As[nxt][ca+1][64+ra] = a1.y;
            As[nxt][ca+2][64+ra] = a1.z; As[nxt][ca+3][64+ra] = a1.w;
            *(float4*)(&Bs[nxt][kb][nb])   = b0;
            *(float4*)(&Bs[nxt][kb][nb+4]) = b1;
        }
        __syncthreads();
    }

    // epilogue: fold BN, write transposed [b][w][row][c]
    float sc[8], sh[8];
    #pragma unroll
    for (int c = 0; c < 8; c++) {
        const int ch = colbase + tx*8 + c;
        const float s = P[ch] * rsqrtf(P[3*ncols + ch] + EPS);
        sc[c] = s;
        sh[c] = P[ncols + ch] - P[2*ncols + ch] * s;
    }
    #pragma unroll
    for (int r = 0; r < 8; r++) {
        const int m   = m0 + ty*8 + r;
        const int b   = m / 3136;
        const int rem = m - b*3136;
        const int i   = rem / 56;
        const int w   = rem - i*56;
        float* drow = dst + (((b*56 + w)*56 + i) * ncols + colbase + tx*8);
        float4 o0, o1;
        o0.x = fmaf(acc[r][0], sc[0], sh[0]); o0.y = fmaf(acc[r][1], sc[1], sh[1]);
        o0.z = fmaf(acc[r][2], sc[2], sh[2]); o0.w = fmaf(acc[r][3], sc[3], sh[3]);
        o1.x = fmaf(acc[r][4], sc[4], sh[4]); o1.y = fmaf(acc[r][5], sc[5], sh[5]);
        o1.z = fmaf(acc[r][6], sc[6], sh[6]); o1.w = fmaf(acc[r][7], sc[7], sh[7]);
        *(float4*)drow     = o0;
        *(float4*)(drow+4) = o1;
    }
}

// ---------------------------------------------------------------------------
// k2: logits per (b,w). L[g][i][j] = s_qk*<q_i,k_j> + s_qr*<q_i,qrel[55+i-j]>
//                                  + s_kr*<k_j,krel[55+j-i]> + t_sum
// ---------------------------------------------------------------------------
__global__ __launch_bounds__(256) void logits_kernel(
    const float* __restrict__ q_rel, const float* __restrict__ k_rel,
    const float* __restrict__ pqk, const float* __restrict__ pqr, const float* __restrict__ pkr)
{
    __shared__ float qg_s[56][36];
    __shared__ float kg_s[56][36];
    __shared__ float qrel_s[111][36];
    __shared__ float krel_s[111][36];

    const int tid = threadIdx.x;
    const int bw  = blockIdx.x;            // b*56 + w

    for (int idx = tid; idx < 111*32; idx += 256) {
        const int d = idx >> 5, c = idx & 31;
        qrel_s[d][c] = q_rel[idx];
        krel_s[d][c] = k_rel[idx];
    }

    const float* qbase = g_Q + bw * 56 * 256;
    const float* kbase = g_K + bw * 56 * 256;

    const bool active = tid < 196;
    const int  ti = tid / 14, tj = tid % 14;
    const int  i0 = ti*4, j0 = tj*4;
    const int  dq0 = 55 + i0 - j0;         // in [3,107] -> +-3 stays in [0,110]
    const int  dk0 = 55 + j0 - i0;

    for (int g = 0; g < 8; g++) {
        __syncthreads();
        for (int idx = tid; idx < 56*32; idx += 256) {
            const int i = idx >> 5, c = idx & 31;
            qg_s[i][c] = qbase[i*256 + g*32 + c];
            kg_s[i][c] = kbase[i*256 + g*32 + c];
        }
        __syncthreads();
        if (!active) continue;

        const float sqk = pqk[g] * rsqrtf(pqk[24+g] + EPS);
        const float sqr = pqr[g] * rsqrtf(pqr[24+g] + EPS);
        const float skr = pkr[g] * rsqrtf(pkr[24+g] + EPS);
        const float tsum = (pqk[8+g] - pqk[16+g]*sqk)
                         + (pqr[8+g] - pqr[16+g]*sqr)
                         + (pkr[8+g] - pkr[16+g]*skr);

        float aqk[4][4], aqr[4][4], akr[4][4];
        #pragma unroll
        for (int a = 0; a < 4; a++)
            #pragma unroll
            for (int b2 = 0; b2 < 4; b2++) { aqk[a][b2]=0.f; aqr[a][b2]=0.f; akr[a][b2]=0.f; }

        #pragma unroll
        for (int c4 = 0; c4 < 32; c4 += 4) {
            float4 qa[4], kb[4];
            #pragma unroll
            for (int a = 0; a < 4; a++) {
                qa[a] = *(const float4*)&qg_s[i0+a][c4];
                kb[a] = *(const float4*)&kg_s[j0+a][c4];
            }
            #pragma unroll
            for (int a = 0; a < 4; a++)
                #pragma unroll
                for (int b2 = 0; b2 < 4; b2++)
                    aqk[a][b2] += dot4(qa[a], kb[b2]);
            {
                float4 r7[7];
                #pragma unroll
                for (int t = 0; t < 7; t++) r7[t] = *(const float4*)&qrel_s[dq0-3+t][c4];
                #pragma unroll
                for (int a = 0; a < 4; a++)
                    #pragma unroll
                    for (int b2 = 0; b2 < 4; b2++)
                        aqr[a][b2] += dot4(qa[a], r7[3 + a - b2]);
            }
            {
                float4 r7[7];
                #pragma unroll
                for (int t = 0; t < 7; t++) r7[t] = *(const float4*)&krel_s[dk0-3+t][c4];
                #pragma unroll
                for (int a = 0; a < 4; a++)
                    #pragma unroll
                    for (int b2 = 0; b2 < 4; b2++)
                        akr[a][b2] += dot4(kb[b2], r7[3 + b2 - a]);
            }
        }

        float* Lp = g_L + ((size_t)bw*8 + g)*3136;
        #pragma unroll
        for (int a = 0; a < 4; a++) {
            float4 o;
            o.x = sqk*aqk[a][0] + sqr*aqr[a][0] + skr*akr[a][0] + tsum;
            o.y = sqk*aqk[a][1] + sqr*aqr[a][1] + skr*akr[a][1] + tsum;
            o.z = sqk*aqk[a][2] + sqr*aqr[a][2] + skr*akr[a][2] + tsum;
            o.w = sqk*aqk[a][3] + sqr*aqr[a][3] + skr*akr[a][3] + tsum;
            *(float4*)&Lp[(i0+a)*56 + j0] = o;
        }
    }
}

// ---------------------------------------------------------------------------
// k3: softmax over w (axis=-2), in place. one thread = one (b,g,ij) column.
// ---------------------------------------------------------------------------
__global__ __launch_bounds__(64) void softmax_kernel()
{
    const int t  = threadIdx.x;
    const int ij = blockIdx.x * 64 + t;
    const int g  = blockIdx.y;
    const int b  = blockIdx.z;
    float* base = g_L + ((size_t)b*448 + g)*3136 + ij;   // 448 = 56*8
    const int ws = 8*3136;

    float v[56];
    float mx = -3.4e38f;
    #pragma unroll
    for (int w = 0; w < 56; w++) { v[w] = base[w*ws]; mx = fmaxf(mx, v[w]); }
    float s = 0.f;
    #pragma unroll
    for (int w = 0; w < 56; w++) { v[w] = __expf(v[w] - mx); s += v[w]; }
    const float inv = 1.f / s;
    #pragma unroll
    for (int w = 0; w < 56; w++) base[w*ws] = v[w] * inv;
}

// ---------------------------------------------------------------------------
// k4: per (b,w): sv[i][ch] = sum_j sim[g][i][j] * V[j][ch]
//                sve[i][ch] = sum_j sim[g][i][j] * vrel[55+j-i][c]
//     out = bn(sv,p_sv) + bn(sve,p_sve),   out layout [b][i][w][512]
// ---------------------------------------------------------------------------
__global__ __launch_bounds__(256) void attn_out_kernel(
    const float* __restrict__ v_rel,
    const float* __restrict__ psv, const float* __restrict__ psve,
    float* __restrict__ out)
{
    extern __shared__ float sm[];
    float* Vsm    = sm;                  // [56][512]
    float* vrel_s = sm + 56*512;         // [111][64]
    float* sim_s  = vrel_s + 111*64;     // [56][56]

    const int tid = threadIdx.x;
    const int bw  = blockIdx.x;
    const int b   = bw / 56, w = bw - b*56;

    const float* vsrc = g_V + (size_t)bw * (56*512);
    for (int idx = tid; idx < 56*512; idx += 256) Vsm[idx] = vsrc[idx];
    for (int idx = tid; idx < 111*64; idx += 256) vrel_s[idx] = v_rel[idx];

    const bool active = tid < 224;
    const int  ti = tid >> 4, tc = tid & 15;
    const int  i0 = ti*4, c0 = tc*4;

    for (int g = 0; g < 8; g++) {
        __syncthreads();
        const float* simsrc = g_L + ((size_t)bw*8 + g)*3136;
        for (int idx = tid; idx < 3136; idx += 256) sim_s[idx] = simsrc[idx];
        __syncthreads();
        if (!active) continue;

        const int ch0 = g*64 + c0;
        float asv[4][4], asve[4][4];
        #pragma unroll
        for (int a = 0; a < 4; a++)
            #pragma unroll
            for (int c = 0; c < 4; c++) { asv[a][c]=0.f; asve[a][c]=0.f; }

        #pragma unroll 4
        for (int j = 0; j < 56; j++) {
            const float4 vv = *(const float4*)&Vsm[j*512 + ch0];
            #pragma unroll
            for (int a = 0; a < 4; a++) {
                const float s = sim_s[(i0+a)*56 + j];
                asv[a][0] = fmaf(s, vv.x, asv[a][0]);
                asv[a][1] = fmaf(s, vv.y, asv[a][1]);
                asv[a][2] = fmaf(s, vv.z, asv[a][2]);
                asv[a][3] = fmaf(s, vv.w, asv[a][3]);
            }
        }
        // d = 55 + j - i ; only d in [52-i0, 110-i0] touches this i-tile
        for (int d = 52 - i0; d <= 110 - i0; d++) {
            const float4 vr = *(const float4*)&vrel_s[d*64 + c0];
            #pragma unroll
            for (int a = 0; a < 4; a++) {
                const int j = i0 + a + d - 55;
                if ((unsigned)j < 56u) {
                    const float s = sim_s[(i0+a)*56 + j];
                    asve[a][0] = fmaf(s, vr.x, asve[a][0]);
                    asve[a][1] = fmaf(s, vr.y, asve[a][1]);
                    asve[a][2] = fmaf(s, vr.z, asve[a][2]);
                    asve[a][3] = fmaf(s, vr.w, asve[a][3]);
                }
            }
        }

        float s1[4], t1[4], s2[4], t2[4];
        #pragma unroll
        for (int cc = 0; cc < 4; cc++) {
            const int ch = ch0 + cc;
            const float a1 = psv[ch] * rsqrtf(psv[1536+ch] + EPS);
            s1[cc] = a1; t1[cc] = psv[512+ch] - psv[1024+ch]*a1;
            const float a2 = psve[ch] * rsqrtf(psve[1536+ch] + EPS);
            s2[cc] = a2; t2[cc] = psve[512+ch] - psve[1024+ch]*a2;
        }
        #pragma unroll
        for (int a = 0; a < 4; a++) {
            float4 o;
            o.x = asv[a][0]*s1[0] + t1[0] + asve[a][0]*s2[0] + t2[0];
            o.y = asv[a][1]*s1[1] + t1[1] + asve[a][1]*s2[1] + t2[1];
            o.z = asv[a][2]*s1[2] + t1[2] + asve[a][2]*s2[2] + t2[2];
            o.w = asv[a][3]*s1[3] + t1[3] + asve[a][3]*s2[3] + t2[3];
            *(float4*)&out[(((b*56 + i0 + a)*56 + w) * 512) + ch0] = o;
        }
    }
}

// ---------------------------------------------------------------------------
extern "C" void kernel_launch(void* const* d_in, const int* in_sizes, int n_in,
                              void* d_out, int out_size)
{
    const float* x     = (const float*)d_in[0];
    const float* Wq    = (const float*)d_in[1];
    const float* Wk    = (const float*)d_in[2];
    const float* Wv    = (const float*)d_in[3];
    const float* q_rel = (const float*)d_in[4];
    const float* k_rel = (const float*)d_in[5];
    const float* v_rel = (const float*)d_in[6];
    const float* p_q   = (const float*)d_in[7];
    const float* p_k   = (const float*)d_in[8];
    const float* p_v   = (const float*)d_in[9];
    const float* p_qk  = (const float*)d_in[10];
    const float* p_qr  = (const float*)d_in[11];
    const float* p_kr  = (const float*)d_in[12];
    const float* p_sv  = (const float*)d_in[13];
    const float* p_sve = (const float*)d_in[14];
    float* out = (float*)d_out;

    const int smem_k4 = (56*512 + 111*64 + 56*56) * 4;   // 155648 B
    cudaFuncSetAttribute(attn_out_kernel,
                         cudaFuncAttributeMaxDynamicSharedMemorySize, smem_k4);

    qkv_gemm_kernel<<<dim3(8, 392), 256>>>(x, Wq, Wk, Wv, p_q, p_k, p_v);
    logits_kernel<<<896, 256>>>(q_rel, k_rel, p_qk, p_qr, p_kr);
    softmax_kernel<<<dim3(49, 8, 16), 64>>>();
    attn_out_kernel<<<896, 256, smem_k4>>>(v_rel, p_sv, p_sve, out);
}